// round 14
// baseline (speedup 1.0000x reference)
#include <cuda_runtime.h>
#include <cuda_fp16.h>
#include <cstdint>

// Problem constants
#define BATCH  16
#define CCH    384
#define HW     4096
#define NHEADS 12
#define DHEAD  32
#define QKV_C  1152

#define BK     64
#define NCHUNK (CCH / BK)   // 6

// ---------------------------------------------------------------------------
// Device-global scratch (no cudaMalloc allowed)
// ---------------------------------------------------------------------------
__device__ __align__(256) __half g_qkv[(size_t)BATCH * HW * QKV_C]; // fp16, q pre-scaled
__device__ __align__(256) __half g_xt[(size_t)BATCH * HW * CCH];    // x^T fp16 [b][pix][c]
__device__ __align__(256) __half g_o [(size_t)BATCH * HW * CCH];    // attn out fp16
__device__ __align__(256) __half g_wq_h[QKV_C * CCH];
__device__ __align__(256) __half g_wp_h[CCH * CCH];

// ---------------------------------------------------------------------------
// Helpers
// ---------------------------------------------------------------------------
__device__ __forceinline__ uint32_t smem_u32(const void* p) {
    uint32_t a;
    asm("{ .reg .u64 t; cvta.to.shared.u64 t, %1; cvt.u32.u64 %0, t; }"
        : "=r"(a) : "l"(p));
    return a;
}

__device__ __forceinline__ uint32_t pack_half2(float a, float b) {
    __half ha = __float2half_rn(a), hb = __float2half_rn(b);
    uint16_t ua = *reinterpret_cast<uint16_t*>(&ha);
    uint16_t ub = *reinterpret_cast<uint16_t*>(&hb);
    return (uint32_t)ua | ((uint32_t)ub << 16);
}

// 32-col tile swizzle (attn): rows of 32 halves (64B), 4x16B chunks
__device__ __forceinline__ uint32_t swz(uint32_t row, uint32_t c16) {
    return row * 64u + ((c16 ^ ((row >> 1) & 3u)) * 16u);
}

// 64-col tile swizzle (gemm): rows of 64 halves (128B), 8x16B chunks
__device__ __forceinline__ uint32_t swz128(uint32_t row, uint32_t c16) {
    return row * 128u + ((c16 ^ (row & 7u)) * 16u);
}

__device__ __forceinline__ void ldm_x4(uint32_t* r, uint32_t addr) {
    asm volatile("ldmatrix.sync.aligned.m8n8.x4.shared.b16 {%0,%1,%2,%3}, [%4];"
                 : "=r"(r[0]), "=r"(r[1]), "=r"(r[2]), "=r"(r[3]) : "r"(addr));
}

__device__ __forceinline__ void ldm_x4_trans(uint32_t* r, uint32_t addr) {
    asm volatile("ldmatrix.sync.aligned.m8n8.x4.trans.shared.b16 {%0,%1,%2,%3}, [%4];"
                 : "=r"(r[0]), "=r"(r[1]), "=r"(r[2]), "=r"(r[3]) : "r"(addr));
}

__device__ __forceinline__ void mma16816h(float* c, const uint32_t* a, const uint32_t* b) {
    asm volatile(
        "mma.sync.aligned.m16n8k16.row.col.f32.f16.f16.f32 "
        "{%0,%1,%2,%3}, {%4,%5,%6,%7}, {%8,%9}, {%0,%1,%2,%3};"
        : "+f"(c[0]), "+f"(c[1]), "+f"(c[2]), "+f"(c[3])
        : "r"(a[0]), "r"(a[1]), "r"(a[2]), "r"(a[3]), "r"(b[0]), "r"(b[1]));
}

#define CP_ASYNC16(dst, src) \
    asm volatile("cp.async.cg.shared.global [%0], [%1], 16;" :: "r"(dst), "l"(src))
#define CP_COMMIT() asm volatile("cp.async.commit_group;")
#define CP_WAIT0()  asm volatile("cp.async.wait_group 0;")
#define CP_WAIT1()  asm volatile("cp.async.wait_group 1;")

// load one 128x64 fp16 tile (row stride CCH) into swizzled smem via cp.async
// 1024 chunks of 16B; 128 threads x 8
__device__ __forceinline__ void load_tile64_async(const __half* __restrict__ src,
                                                  int row0, int k0, uint32_t dst, int tid) {
    #pragma unroll
    for (int j = 0; j < 8; j++) {
        int c   = tid + j * 128;
        int row = c >> 3, c16 = c & 7;
        const __half* g = src + (size_t)(row0 + row) * CCH + k0 + c16 * 8;
        CP_ASYNC16(dst + swz128((uint32_t)row, (uint32_t)c16), g);
    }
}

// ---------------------------------------------------------------------------
// Kernel 1: transpose x [b][c][pix] -> fp16 [b][pix][c].
// Extra z-slice (b == BATCH) converts both weight matrices to fp16.
// ---------------------------------------------------------------------------
__global__ __launch_bounds__(256) void transpose_half_kernel(const float* __restrict__ x,
                                                             const float* __restrict__ wq,
                                                             const float* __restrict__ wp)
{
    const int b = blockIdx.z;
    if (b == BATCH) {
        int nblk = gridDim.x * gridDim.y;
        int bid  = blockIdx.y * gridDim.x + blockIdx.x;
        int stride = nblk * 256;
        for (int i = bid * 256 + threadIdx.x; i < QKV_C * CCH; i += stride)
            g_wq_h[i] = __float2half_rn(wq[i]);
        for (int i = bid * 256 + threadIdx.x; i < CCH * CCH; i += stride)
            g_wp_h[i] = __float2half_rn(wp[i]);
        return;
    }

    __shared__ float t[32][33];
    const int p0 = blockIdx.x * 32;
    const int c0 = blockIdx.y * 32;
    const int tx = threadIdx.x & 31;
    const int ty = threadIdx.x >> 5;

    const float* xb = x + (size_t)b * CCH * HW;
    #pragma unroll
    for (int i = 0; i < 4; i++)
        t[ty + i * 8][tx] = xb[(size_t)(c0 + ty + i * 8) * HW + p0 + tx];
    __syncthreads();

    #pragma unroll
    for (int i = 0; i < 4; i++) {
        int p = p0 + ty + i * 8;
        int c = c0 + tx;
        g_xt[((size_t)b * HW + p) * CCH + c] = __float2half_rn(t[tx][ty + i * 8]);
    }
}

// ---------------------------------------------------------------------------
// Tensor-core GEMM (single-pass fp16 mma, fp32 accumulate)  — R11 config
// D[pix(128)][och(128)] = A[pix][cch] . B[och][cch]^T
// 4 warps, warp tile 64x64. BK=64, 3-stage cp.async pipeline (32KB/stage).
// G==0: A = g_xt, B = w_qkv -> g_qkv fp16 [b][pix][1152], q cols pre-scaled
// G==1: A = g_o,  B = w_proj -> out  fp32 [b][och][4096]
// ---------------------------------------------------------------------------
#define STAGE_BYTES 32768
#define GEMM_SMEM   98304

template<int G>
__global__ __launch_bounds__(128, 2) void gemm_mma_kernel(const float* __restrict__ bias,
                                                          float* __restrict__ out_base)
{
    extern __shared__ __align__(128) char smem[];
    const uint32_t sbase = smem_u32(smem);
    const int tid = threadIdx.x, wid = tid >> 5, lane = tid & 31;
    const int warp_m = wid & 1;        // 2 warps along m (64 rows each)
    const int warp_n = wid >> 1;       // 2 warps along n (64 cols each)

    const int b  = blockIdx.z;
    const int n0 = blockIdx.x * 128;   // och tile (x fastest -> A reuse in L2)
    const int m0 = blockIdx.y * 128;   // pixel tile

    const __half* A  = (G == 0 ? g_xt : g_o) + (size_t)b * HW * CCH;
    const __half* Bw = (G == 0 ? g_wq_h : g_wp_h);

    float acc[4][8][4] = {};

    #pragma unroll
    for (int i = 0; i < 2; i++) {
        const uint32_t sb = sbase + i * STAGE_BYTES;
        load_tile64_async(A,  m0, i * BK, sb + 0,     tid);
        load_tile64_async(Bw, n0, i * BK, sb + 16384, tid);
        CP_COMMIT();
    }
    CP_WAIT1();
    __syncthreads();

    const int lrow = lane & 7;
    const int lblk = lane >> 3;

    #pragma unroll 1
    for (int i = 0; i < NCHUNK; i++) {
        if (i + 2 < NCHUNK) {
            const uint32_t nb = sbase + ((i + 2) % 3) * STAGE_BYTES;
            const int k0 = (i + 2) * BK;
            load_tile64_async(A,  m0, k0, nb + 0,     tid);
            load_tile64_async(Bw, n0, k0, nb + 16384, tid);
            CP_COMMIT();
        }

        const uint32_t sA = sbase + (i % 3) * STAGE_BYTES;
        const uint32_t sB = sA + 16384;

        #pragma unroll
        for (int ks = 0; ks < 4; ks++) {
            uint32_t Af[4][4];
            #pragma unroll
            for (int mt = 0; mt < 4; mt++) {
                uint32_t row = (uint32_t)(warp_m * 64 + mt * 16 + (lblk & 1) * 8 + lrow);
                uint32_t c16 = (uint32_t)(ks * 2 + (lblk >> 1));
                ldm_x4(Af[mt], sA + swz128(row, c16));
            }
            uint32_t Bf[8][2];
            #pragma unroll
            for (int np = 0; np < 4; np++) {
                uint32_t row = (uint32_t)(warp_n * 64 + np * 16 + (lblk >> 1) * 8 + lrow);
                uint32_t c16 = (uint32_t)(ks * 2 + (lblk & 1));
                uint32_t r[4];
                ldm_x4(r, sB + swz128(row, c16));
                Bf[np*2][0] = r[0]; Bf[np*2][1] = r[1];
                Bf[np*2+1][0] = r[2]; Bf[np*2+1][1] = r[3];
            }
            #pragma unroll
            for (int mt = 0; mt < 4; mt++)
                #pragma unroll
                for (int nt = 0; nt < 8; nt++)
                    mma16816h(acc[mt][nt], Af[mt], Bf[nt]);
        }

        if (i + 2 < NCHUNK)      CP_WAIT1();
        else if (i + 1 < NCHUNK) CP_WAIT0();
        __syncthreads();
    }

    // ------------------- epilogue -------------------
    if (G == 0) {
        constexpr int PADH = 136;   // halves per staged row (272B, 16B-mult)
        const float SCALE = 0.17677669529663687f;
        __half* st = reinterpret_cast<__half*>(smem);   // [128][136]
        {
            #pragma unroll
            for (int mt = 0; mt < 4; mt++)
                #pragma unroll
                for (int nt = 0; nt < 8; nt++) {
                    int ml = warp_m * 64 + mt * 16 + (lane >> 2);
                    int nl = warp_n * 64 + nt * 8 + (lane & 3) * 2;
                    int och = n0 + nl;
                    float s  = (och < CCH) ? SCALE : 1.0f;
                    float b0 = bias[och], b1 = bias[och + 1];
                    *reinterpret_cast<uint32_t*>(&st[ml * PADH + nl]) =
                        pack_half2((acc[mt][nt][0] + b0) * s, (acc[mt][nt][1] + b1) * s);
                    *reinterpret_cast<uint32_t*>(&st[(ml + 8) * PADH + nl]) =
                        pack_half2((acc[mt][nt][2] + b0) * s, (acc[mt][nt][3] + b1) * s);
                }
        }
        __syncthreads();
        __half* outb = g_qkv + (size_t)b * HW * QKV_C;
        #pragma unroll
        for (int j = 0; j < 16; j++) {
            int fi  = tid + j * 128;          // 2048 chunks of 8 halves
            int row = fi >> 4;
            int c16 = fi & 15;
            uint4 v = *reinterpret_cast<uint4*>(&st[row * PADH + c16 * 8]);
            *reinterpret_cast<uint4*>(&outb[(size_t)(m0 + row) * QKV_C + n0 + c16 * 8]) = v;
        }
    } else {
        constexpr int PAD = 132;
        float* st = reinterpret_cast<float*>(smem);     // [64][132]
        float* outb = out_base + (size_t)b * CCH * HW;
        #pragma unroll 1
        for (int h = 0; h < 2; h++) {
            __syncthreads();
            if (warp_n == h) {
                #pragma unroll
                for (int mt = 0; mt < 4; mt++)
                    #pragma unroll
                    for (int nt = 0; nt < 8; nt++) {
                        int ml = warp_m * 64 + mt * 16 + (lane >> 2);
                        int nl = nt * 8 + (lane & 3) * 2;
                        st[nl * PAD + ml]           = acc[mt][nt][0];
                        st[(nl + 1) * PAD + ml]     = acc[mt][nt][1];
                        st[nl * PAD + ml + 8]       = acc[mt][nt][2];
                        st[(nl + 1) * PAD + ml + 8] = acc[mt][nt][3];
                    }
            }
            __syncthreads();
            #pragma unroll
            for (int j = 0; j < 16; j++) {
                int fi  = tid + j * 128;
                int row = fi >> 5;
                int c4  = (fi & 31) * 4;
                int och = n0 + h * 64 + row;
                float4 v = *reinterpret_cast<float4*>(&st[row * PAD + c4]);
                float bi = bias[och];
                v.x += bi; v.y += bi; v.z += bi; v.w += bi;
                *reinterpret_cast<float4*>(&outb[(size_t)och * HW + m0 + c4]) = v;
            }
        }
    }
}

// ---------------------------------------------------------------------------
// Attention: 1 block = (b, HEAD PAIR, window), 8 warps / 256 threads.
// Warps 0-3 handle head 2*hp, warps 4-7 handle head 2*hp+1.
// Every q/k/v token-row load is a full 128B line (both heads); output store
// writes 128B per token. Per-warp math identical to the R11 kernel.
// ---------------------------------------------------------------------------
__global__ __launch_bounds__(256) void attn_mma_kernel()
{
    __shared__ __align__(128) __half sq[2][64 * 32];
    __shared__ __align__(128) __half sk[2][64 * 32];
    __shared__ __align__(128) __half sv[2][64 * 32];

    const int wi   = blockIdx.x;   // window 0..63
    const int hp   = blockIdx.y;   // head pair 0..5
    const int b    = blockIdx.z;
    const int tid  = threadIdx.x;
    const int wid  = tid >> 5;
    const int lane = tid & 31;
    const int sub  = wid >> 2;     // this warp's head parity (0/1)
    const int w4   = wid & 3;      // warp index within head

    const int hh = wi >> 3;
    const int ww = wi & 7;

    const uint32_t aq = smem_u32(sq), ak = smem_u32(sk), av = smem_u32(sv);

    // base for the head pair: channel offset hp*64 within each tensor
    const __half* base = g_qkv + (size_t)b * HW * QKV_C + (size_t)hp * (2 * DHEAD);

    // ---- cp.async q,k,v (both heads) into swizzled smem ---------------------
    // 1536 chunks of 16B: ten(3) x tok(64) x c8(8). c8 spans 128B = both heads.
    #pragma unroll
    for (int it = 0; it < 6; it++) {
        int c   = tid + it * 256;
        int ten = c >> 9;              // 0=q 1=k 2=v
        int rem = c & 511;
        int tok = rem >> 3;
        int c8  = rem & 7;             // 0-3: even head, 4-7: odd head
        int wsh = tok >> 3, wsw = tok & 7;
        int pix = (wsh * 8 + hh) * 64 + wsw * 8 + ww;
        const __half* g = base + (size_t)pix * QKV_C + ten * CCH + c8 * 8;
        uint32_t dst = (ten == 0 ? aq : ten == 1 ? ak : av)
                     + (uint32_t)(c8 >> 2) * 4096u
                     + swz((uint32_t)tok, (uint32_t)(c8 & 3));
        CP_ASYNC16(dst, g);
    }
    CP_COMMIT();
    CP_WAIT0();
    __syncthreads();

    const int lrow = lane & 7;
    const int lblk = lane >> 3;
    const uint32_t aqw = aq + (uint32_t)sub * 4096u;
    const uint32_t akw = ak + (uint32_t)sub * 4096u;
    const uint32_t avw = av + (uint32_t)sub * 4096u;

    // ---- S = Q K^T (q pre-scaled), single-pass fp16 -------------------------
    float acc[8][4] = {};
    #pragma unroll
    for (int ks = 0; ks < 2; ks++) {
        uint32_t Af[4];
        {
            uint32_t row = (uint32_t)(w4 * 16 + (lblk & 1) * 8 + lrow);
            uint32_t c16 = (uint32_t)(ks * 2 + (lblk >> 1));
            ldm_x4(Af, aqw + swz(row, c16));
        }
        uint32_t Bf[8][2];
        #pragma unroll
        for (int np = 0; np < 4; np++) {
            uint32_t row = (uint32_t)(np * 16 + (lblk >> 1) * 8 + lrow);
            uint32_t c16 = (uint32_t)(ks * 2 + (lblk & 1));
            uint32_t r[4];
            ldm_x4(r, akw + swz(row, c16));
            Bf[np*2][0] = r[0]; Bf[np*2][1] = r[1];
            Bf[np*2+1][0] = r[2]; Bf[np*2+1][1] = r[3];
        }
        #pragma unroll
        for (int nt = 0; nt < 8; nt++) mma16816h(acc[nt], Af, Bf[nt]);
    }

    // ---- softmax in registers ----------------------------------------------
    float mx0 = -1e30f, mx1 = -1e30f;
    #pragma unroll
    for (int nt = 0; nt < 8; nt++) {
        mx0 = fmaxf(mx0, fmaxf(acc[nt][0], acc[nt][1]));
        mx1 = fmaxf(mx1, fmaxf(acc[nt][2], acc[nt][3]));
    }
    #pragma unroll
    for (int d = 1; d <= 2; d <<= 1) {
        mx0 = fmaxf(mx0, __shfl_xor_sync(0xffffffffu, mx0, d));
        mx1 = fmaxf(mx1, __shfl_xor_sync(0xffffffffu, mx1, d));
    }
    float s0 = 0.f, s1 = 0.f;
    #pragma unroll
    for (int nt = 0; nt < 8; nt++) {
        acc[nt][0] = __expf(acc[nt][0] - mx0);
        acc[nt][1] = __expf(acc[nt][1] - mx0);
        acc[nt][2] = __expf(acc[nt][2] - mx1);
        acc[nt][3] = __expf(acc[nt][3] - mx1);
        s0 += acc[nt][0] + acc[nt][1];
        s1 += acc[nt][2] + acc[nt][3];
    }
    #pragma unroll
    for (int d = 1; d <= 2; d <<= 1) {
        s0 += __shfl_xor_sync(0xffffffffu, s0, d);
        s1 += __shfl_xor_sync(0xffffffffu, s1, d);
    }
    const float inv0 = 1.f / s0, inv1 = 1.f / s1;

    // ---- O = P V : single-pass fp16 P (packed straight from acc) ------------
    float o[4][4] = {};
    #pragma unroll
    for (int j = 0; j < 4; j++) {
        uint32_t aP[4];
        aP[0] = pack_half2(acc[2*j][0],   acc[2*j][1]);
        aP[1] = pack_half2(acc[2*j][2],   acc[2*j][3]);
        aP[2] = pack_half2(acc[2*j+1][0], acc[2*j+1][1]);
        aP[3] = pack_half2(acc[2*j+1][2], acc[2*j+1][3]);

        uint32_t Bv[4][2];
        #pragma unroll
        for (int a = 0; a < 2; a++) {
            uint32_t row = (uint32_t)(16 * j + lrow + (lblk & 1) * 8);
            uint32_t c16 = (uint32_t)(2 * a + (lblk >> 1));
            uint32_t r[4];
            ldm_x4_trans(r, avw + swz(row, c16));
            Bv[2*a][0] = r[0]; Bv[2*a][1] = r[1];
            Bv[2*a+1][0] = r[2]; Bv[2*a+1][1] = r[3];
        }
        #pragma unroll
        for (int nt = 0; nt < 4; nt++) mma16816h(o[nt], aP, Bv[nt]);
    }

    // ---- epilogue: normalize, fp16, stage in smem (reuse sq), store ---------
    __syncthreads();
    {
        __half* stw = &sq[sub][0];
        int r0 = 16 * w4 + (lane >> 2);
        int cb = (lane & 3) * 2;
        #pragma unroll
        for (int nt = 0; nt < 4; nt++) {
            int d = nt * 8 + cb;
            *reinterpret_cast<uint32_t*>(&stw[r0 * 32 + d]) =
                pack_half2(o[nt][0] * inv0, o[nt][1] * inv0);
            *reinterpret_cast<uint32_t*>(&stw[(r0 + 8) * 32 + d]) =
                pack_half2(o[nt][2] * inv1, o[nt][3] * inv1);
        }
    }
    __syncthreads();
    {
        // 128B per token (both heads); 4 threads/token x 32B each
        int tok  = tid >> 2;
        int q4   = tid & 3;
        int sub2 = q4 >> 1;
        int seg  = q4 & 1;
        int wsh = tok >> 3, wsw = tok & 7;
        int pixo = (hh * 8 + wsh) * 64 + ww * 8 + wsw;
        size_t off = ((size_t)b * HW + pixo) * CCH + hp * 64 + sub2 * 32 + seg * 16;
        const uint4* s = reinterpret_cast<const uint4*>(&sq[sub2][tok * 32 + seg * 16]);
        uint4* d = reinterpret_cast<uint4*>(g_o + off);
        d[0] = s[0];
        d[1] = s[1];
    }
}

// ---------------------------------------------------------------------------
extern "C" void kernel_launch(void* const* d_in, const int* in_sizes, int n_in,
                              void* d_out, int out_size)
{
    const float* x      = (const float*)d_in[0];
    const float* w_qkv  = (const float*)d_in[1];
    const float* b_qkv  = (const float*)d_in[2];
    const float* w_proj = (const float*)d_in[3];
    const float* b_proj = (const float*)d_in[4];
    float* out = (float*)d_out;
    (void)in_sizes; (void)n_in; (void)out_size;

    cudaFuncSetAttribute(gemm_mma_kernel<0>,
                         cudaFuncAttributeMaxDynamicSharedMemorySize, GEMM_SMEM);
    cudaFuncSetAttribute(gemm_mma_kernel<1>,
                         cudaFuncAttributeMaxDynamicSharedMemorySize, GEMM_SMEM);

    // transpose x + (z-slice BATCH) weight fp16 conversion, one launch
    dim3 gT(HW / 32, CCH / 32, BATCH + 1);
    transpose_half_kernel<<<gT, 256>>>(x, w_qkv, w_proj);

    dim3 g1(QKV_C / 128, HW / 128, BATCH);   // n fastest -> A-tile L2 reuse
    gemm_mma_kernel<0><<<g1, 128, GEMM_SMEM>>>(b_qkv, nullptr);

    dim3 gA(64, NHEADS / 2, BATCH);          // window x head-pair x batch
    attn_mma_kernel<<<gA, 256>>>();

    dim3 g2(CCH / 128, HW / 128, BATCH);
    gemm_mma_kernel<1><<<g2, 128, GEMM_SMEM>>>(b_proj, out);
}

// round 15
// speedup vs baseline: 1.5193x; 1.5193x over previous
#include <cuda_runtime.h>
#include <cuda_fp16.h>
#include <cstdint>

// Problem constants
#define BATCH  16
#define CCH    384
#define HW     4096
#define NHEADS 12
#define DHEAD  32
#define QKV_C  1152

#define BK     64
#define NCHUNK (CCH / BK)   // 6

// ---------------------------------------------------------------------------
// Device-global scratch (no cudaMalloc allowed)
// ---------------------------------------------------------------------------
__device__ __align__(256) __half g_qkv[(size_t)BATCH * HW * QKV_C]; // fp16, q pre-scaled
__device__ __align__(256) __half g_xt[(size_t)BATCH * HW * CCH];    // x^T fp16 [b][pix][c]
__device__ __align__(256) __half g_o [(size_t)BATCH * HW * CCH];    // attn out fp16
__device__ __align__(256) __half g_wq_h[QKV_C * CCH];
__device__ __align__(256) __half g_wp_h[CCH * CCH];

// ---------------------------------------------------------------------------
// Helpers
// ---------------------------------------------------------------------------
__device__ __forceinline__ uint32_t smem_u32(const void* p) {
    uint32_t a;
    asm("{ .reg .u64 t; cvta.to.shared.u64 t, %1; cvt.u32.u64 %0, t; }"
        : "=r"(a) : "l"(p));
    return a;
}

__device__ __forceinline__ uint32_t pack_half2(float a, float b) {
    __half ha = __float2half_rn(a), hb = __float2half_rn(b);
    uint16_t ua = *reinterpret_cast<uint16_t*>(&ha);
    uint16_t ub = *reinterpret_cast<uint16_t*>(&hb);
    return (uint32_t)ua | ((uint32_t)ub << 16);
}

// 32-col tile swizzle (attn): rows of 32 halves (64B), 4x16B chunks
__device__ __forceinline__ uint32_t swz(uint32_t row, uint32_t c16) {
    return row * 64u + ((c16 ^ ((row >> 1) & 3u)) * 16u);
}

// 64-col tile swizzle (gemm): rows of 64 halves (128B), 8x16B chunks
__device__ __forceinline__ uint32_t swz128(uint32_t row, uint32_t c16) {
    return row * 128u + ((c16 ^ (row & 7u)) * 16u);
}

__device__ __forceinline__ void ldm_x4(uint32_t* r, uint32_t addr) {
    asm volatile("ldmatrix.sync.aligned.m8n8.x4.shared.b16 {%0,%1,%2,%3}, [%4];"
                 : "=r"(r[0]), "=r"(r[1]), "=r"(r[2]), "=r"(r[3]) : "r"(addr));
}

__device__ __forceinline__ void ldm_x4_trans(uint32_t* r, uint32_t addr) {
    asm volatile("ldmatrix.sync.aligned.m8n8.x4.trans.shared.b16 {%0,%1,%2,%3}, [%4];"
                 : "=r"(r[0]), "=r"(r[1]), "=r"(r[2]), "=r"(r[3]) : "r"(addr));
}

__device__ __forceinline__ void mma16816h(float* c, const uint32_t* a, const uint32_t* b) {
    asm volatile(
        "mma.sync.aligned.m16n8k16.row.col.f32.f16.f16.f32 "
        "{%0,%1,%2,%3}, {%4,%5,%6,%7}, {%8,%9}, {%0,%1,%2,%3};"
        : "+f"(c[0]), "+f"(c[1]), "+f"(c[2]), "+f"(c[3])
        : "r"(a[0]), "r"(a[1]), "r"(a[2]), "r"(a[3]), "r"(b[0]), "r"(b[1]));
}

#define CP_ASYNC16(dst, src) \
    asm volatile("cp.async.cg.shared.global [%0], [%1], 16;" :: "r"(dst), "l"(src))
#define CP_COMMIT() asm volatile("cp.async.commit_group;")
#define CP_WAIT0()  asm volatile("cp.async.wait_group 0;")
#define CP_WAIT1()  asm volatile("cp.async.wait_group 1;")

// load one 128x64 fp16 tile (row stride CCH) into swizzled smem via cp.async
// 1024 chunks of 16B; 128 threads x 8
__device__ __forceinline__ void load_tile64_async(const __half* __restrict__ src,
                                                  int row0, int k0, uint32_t dst, int tid) {
    #pragma unroll
    for (int j = 0; j < 8; j++) {
        int c   = tid + j * 128;
        int row = c >> 3, c16 = c & 7;
        const __half* g = src + (size_t)(row0 + row) * CCH + k0 + c16 * 8;
        CP_ASYNC16(dst + swz128((uint32_t)row, (uint32_t)c16), g);
    }
}

// ---------------------------------------------------------------------------
// Kernel 1: transpose x [b][c][pix] -> fp16 [b][pix][c].
// Extra z-slice (b == BATCH) converts both weight matrices to fp16.
// ---------------------------------------------------------------------------
__global__ __launch_bounds__(256) void transpose_half_kernel(const float* __restrict__ x,
                                                             const float* __restrict__ wq,
                                                             const float* __restrict__ wp)
{
    const int b = blockIdx.z;
    if (b == BATCH) {
        int nblk = gridDim.x * gridDim.y;
        int bid  = blockIdx.y * gridDim.x + blockIdx.x;
        int stride = nblk * 256;
        for (int i = bid * 256 + threadIdx.x; i < QKV_C * CCH; i += stride)
            g_wq_h[i] = __float2half_rn(wq[i]);
        for (int i = bid * 256 + threadIdx.x; i < CCH * CCH; i += stride)
            g_wp_h[i] = __float2half_rn(wp[i]);
        return;
    }

    __shared__ float t[32][33];
    const int p0 = blockIdx.x * 32;
    const int c0 = blockIdx.y * 32;
    const int tx = threadIdx.x & 31;
    const int ty = threadIdx.x >> 5;

    const float* xb = x + (size_t)b * CCH * HW;
    #pragma unroll
    for (int i = 0; i < 4; i++)
        t[ty + i * 8][tx] = xb[(size_t)(c0 + ty + i * 8) * HW + p0 + tx];
    __syncthreads();

    #pragma unroll
    for (int i = 0; i < 4; i++) {
        int p = p0 + ty + i * 8;
        int c = c0 + tx;
        g_xt[((size_t)b * HW + p) * CCH + c] = __float2half_rn(t[tx][ty + i * 8]);
    }
}

// ---------------------------------------------------------------------------
// Tensor-core GEMM (single-pass fp16 mma, fp32 accumulate)  — R11 config
// D[pix(128)][och(128)] = A[pix][cch] . B[och][cch]^T
// 4 warps, warp tile 64x64. BK=64, 3-stage cp.async pipeline (32KB/stage).
// G==0: A = g_xt, B = w_qkv -> g_qkv fp16 [b][pix][1152], q cols pre-scaled
// G==1: A = g_o,  B = w_proj -> out  fp32 [b][och][4096]
// ---------------------------------------------------------------------------
#define STAGE_BYTES 32768
#define GEMM_SMEM   98304

template<int G>
__global__ __launch_bounds__(128, 2) void gemm_mma_kernel(const float* __restrict__ bias,
                                                          float* __restrict__ out_base)
{
    extern __shared__ __align__(128) char smem[];
    const uint32_t sbase = smem_u32(smem);
    const int tid = threadIdx.x, wid = tid >> 5, lane = tid & 31;
    const int warp_m = wid & 1;        // 2 warps along m (64 rows each)
    const int warp_n = wid >> 1;       // 2 warps along n (64 cols each)

    const int b  = blockIdx.z;
    const int n0 = blockIdx.x * 128;   // och tile (x fastest -> A reuse in L2)
    const int m0 = blockIdx.y * 128;   // pixel tile

    const __half* A  = (G == 0 ? g_xt : g_o) + (size_t)b * HW * CCH;
    const __half* Bw = (G == 0 ? g_wq_h : g_wp_h);

    float acc[4][8][4] = {};

    #pragma unroll
    for (int i = 0; i < 2; i++) {
        const uint32_t sb = sbase + i * STAGE_BYTES;
        load_tile64_async(A,  m0, i * BK, sb + 0,     tid);
        load_tile64_async(Bw, n0, i * BK, sb + 16384, tid);
        CP_COMMIT();
    }
    CP_WAIT1();
    __syncthreads();

    const int lrow = lane & 7;
    const int lblk = lane >> 3;

    #pragma unroll 1
    for (int i = 0; i < NCHUNK; i++) {
        if (i + 2 < NCHUNK) {
            const uint32_t nb = sbase + ((i + 2) % 3) * STAGE_BYTES;
            const int k0 = (i + 2) * BK;
            load_tile64_async(A,  m0, k0, nb + 0,     tid);
            load_tile64_async(Bw, n0, k0, nb + 16384, tid);
            CP_COMMIT();
        }

        const uint32_t sA = sbase + (i % 3) * STAGE_BYTES;
        const uint32_t sB = sA + 16384;

        #pragma unroll
        for (int ks = 0; ks < 4; ks++) {
            uint32_t Af[4][4];
            #pragma unroll
            for (int mt = 0; mt < 4; mt++) {
                uint32_t row = (uint32_t)(warp_m * 64 + mt * 16 + (lblk & 1) * 8 + lrow);
                uint32_t c16 = (uint32_t)(ks * 2 + (lblk >> 1));
                ldm_x4(Af[mt], sA + swz128(row, c16));
            }
            uint32_t Bf[8][2];
            #pragma unroll
            for (int np = 0; np < 4; np++) {
                uint32_t row = (uint32_t)(warp_n * 64 + np * 16 + (lblk >> 1) * 8 + lrow);
                uint32_t c16 = (uint32_t)(ks * 2 + (lblk & 1));
                uint32_t r[4];
                ldm_x4(r, sB + swz128(row, c16));
                Bf[np*2][0] = r[0]; Bf[np*2][1] = r[1];
                Bf[np*2+1][0] = r[2]; Bf[np*2+1][1] = r[3];
            }
            #pragma unroll
            for (int mt = 0; mt < 4; mt++)
                #pragma unroll
                for (int nt = 0; nt < 8; nt++)
                    mma16816h(acc[mt][nt], Af[mt], Bf[nt]);
        }

        if (i + 2 < NCHUNK)      CP_WAIT1();
        else if (i + 1 < NCHUNK) CP_WAIT0();
        __syncthreads();
    }

    // ------------------- epilogue -------------------
    if (G == 0) {
        constexpr int PADH = 136;   // halves per staged row (272B, 16B-mult)
        const float SCALE = 0.17677669529663687f;
        __half* st = reinterpret_cast<__half*>(smem);   // [128][136]
        {
            #pragma unroll
            for (int mt = 0; mt < 4; mt++)
                #pragma unroll
                for (int nt = 0; nt < 8; nt++) {
                    int ml = warp_m * 64 + mt * 16 + (lane >> 2);
                    int nl = warp_n * 64 + nt * 8 + (lane & 3) * 2;
                    int och = n0 + nl;
                    float s  = (och < CCH) ? SCALE : 1.0f;
                    float b0 = bias[och], b1 = bias[och + 1];
                    *reinterpret_cast<uint32_t*>(&st[ml * PADH + nl]) =
                        pack_half2((acc[mt][nt][0] + b0) * s, (acc[mt][nt][1] + b1) * s);
                    *reinterpret_cast<uint32_t*>(&st[(ml + 8) * PADH + nl]) =
                        pack_half2((acc[mt][nt][2] + b0) * s, (acc[mt][nt][3] + b1) * s);
                }
        }
        __syncthreads();
        __half* outb = g_qkv + (size_t)b * HW * QKV_C;
        #pragma unroll
        for (int j = 0; j < 16; j++) {
            int fi  = tid + j * 128;          // 2048 chunks of 8 halves
            int row = fi >> 4;
            int c16 = fi & 15;
            uint4 v = *reinterpret_cast<uint4*>(&st[row * PADH + c16 * 8]);
            *reinterpret_cast<uint4*>(&outb[(size_t)(m0 + row) * QKV_C + n0 + c16 * 8]) = v;
        }
    } else {
        constexpr int PAD = 132;
        float* st = reinterpret_cast<float*>(smem);     // [64][132]
        float* outb = out_base + (size_t)b * CCH * HW;
        #pragma unroll 1
        for (int h = 0; h < 2; h++) {
            __syncthreads();
            if (warp_n == h) {
                #pragma unroll
                for (int mt = 0; mt < 4; mt++)
                    #pragma unroll
                    for (int nt = 0; nt < 8; nt++) {
                        int ml = warp_m * 64 + mt * 16 + (lane >> 2);
                        int nl = nt * 8 + (lane & 3) * 2;
                        st[nl * PAD + ml]           = acc[mt][nt][0];
                        st[(nl + 1) * PAD + ml]     = acc[mt][nt][1];
                        st[nl * PAD + ml + 8]       = acc[mt][nt][2];
                        st[(nl + 1) * PAD + ml + 8] = acc[mt][nt][3];
                    }
            }
            __syncthreads();
            #pragma unroll
            for (int j = 0; j < 16; j++) {
                int fi  = tid + j * 128;
                int row = fi >> 5;
                int c4  = (fi & 31) * 4;
                int och = n0 + h * 64 + row;
                float4 v = *reinterpret_cast<float4*>(&st[row * PAD + c4]);
                float bi = bias[och];
                v.x += bi; v.y += bi; v.z += bi; v.w += bi;
                *reinterpret_cast<float4*>(&outb[(size_t)och * HW + m0 + c4]) = v;
            }
        }
    }
}

// ---------------------------------------------------------------------------
// Attention: 1 block = (b, head, window), 4 warps. All-fp16 operands.
// q pre-scaled by producer. S single-pass; P·V single-pass fp16 (P in [0,1]).
// Strided windows (faithful to reference).
// ---------------------------------------------------------------------------
__global__ __launch_bounds__(128) void attn_mma_kernel()
{
    __shared__ __align__(128) __half sq[64 * 32];
    __shared__ __align__(128) __half sk[64 * 32];
    __shared__ __align__(128) __half sv[64 * 32];

    const int wi   = blockIdx.x;
    const int head = blockIdx.y;
    const int b    = blockIdx.z;
    const int hh   = wi >> 3;
    const int ww   = wi & 7;
    const int tid  = threadIdx.x;
    const int wid  = tid >> 5;
    const int lane = tid & 31;

    const uint32_t aq = smem_u32(sq), ak = smem_u32(sk), av = smem_u32(sv);

    const __half* base = g_qkv + (size_t)b * HW * QKV_C + (size_t)head * DHEAD;

    // ---- cp.async q,k,v straight into swizzled smem -------------------------
    #pragma unroll
    for (int it = 0; it < 6; it++) {
        int e   = tid + it * 128;
        int ten = e >> 8;              // 0=q 1=k 2=v
        int rem = e & 255;
        int tok = rem >> 2;
        int c16 = rem & 3;
        int wsh = tok >> 3, wsw = tok & 7;
        int pix = (wsh * 8 + hh) * 64 + wsw * 8 + ww;
        const __half* g = base + (size_t)pix * QKV_C + ten * CCH + c16 * 8;
        uint32_t dst = (ten == 0 ? aq : ten == 1 ? ak : av) + swz((uint32_t)tok, (uint32_t)c16);
        CP_ASYNC16(dst, g);
    }
    CP_COMMIT();
    CP_WAIT0();
    __syncthreads();

    const int lrow = lane & 7;
    const int lblk = lane >> 3;

    // ---- S = Q K^T (q pre-scaled), single-pass fp16 -------------------------
    float acc[8][4] = {};
    #pragma unroll
    for (int ks = 0; ks < 2; ks++) {
        uint32_t Af[4];
        {
            uint32_t row = (uint32_t)(wid * 16 + (lblk & 1) * 8 + lrow);
            uint32_t c16 = (uint32_t)(ks * 2 + (lblk >> 1));
            ldm_x4(Af, aq + swz(row, c16));
        }
        uint32_t Bf[8][2];
        #pragma unroll
        for (int np = 0; np < 4; np++) {
            uint32_t row = (uint32_t)(np * 16 + (lblk >> 1) * 8 + lrow);
            uint32_t c16 = (uint32_t)(ks * 2 + (lblk & 1));
            uint32_t r[4];
            ldm_x4(r, ak + swz(row, c16));
            Bf[np*2][0] = r[0]; Bf[np*2][1] = r[1];
            Bf[np*2+1][0] = r[2]; Bf[np*2+1][1] = r[3];
        }
        #pragma unroll
        for (int nt = 0; nt < 8; nt++) mma16816h(acc[nt], Af, Bf[nt]);
    }

    // ---- softmax in registers ----------------------------------------------
    float mx0 = -1e30f, mx1 = -1e30f;
    #pragma unroll
    for (int nt = 0; nt < 8; nt++) {
        mx0 = fmaxf(mx0, fmaxf(acc[nt][0], acc[nt][1]));
        mx1 = fmaxf(mx1, fmaxf(acc[nt][2], acc[nt][3]));
    }
    #pragma unroll
    for (int d = 1; d <= 2; d <<= 1) {
        mx0 = fmaxf(mx0, __shfl_xor_sync(0xffffffffu, mx0, d));
        mx1 = fmaxf(mx1, __shfl_xor_sync(0xffffffffu, mx1, d));
    }
    float s0 = 0.f, s1 = 0.f;
    #pragma unroll
    for (int nt = 0; nt < 8; nt++) {
        acc[nt][0] = __expf(acc[nt][0] - mx0);
        acc[nt][1] = __expf(acc[nt][1] - mx0);
        acc[nt][2] = __expf(acc[nt][2] - mx1);
        acc[nt][3] = __expf(acc[nt][3] - mx1);
        s0 += acc[nt][0] + acc[nt][1];
        s1 += acc[nt][2] + acc[nt][3];
    }
    #pragma unroll
    for (int d = 1; d <= 2; d <<= 1) {
        s0 += __shfl_xor_sync(0xffffffffu, s0, d);
        s1 += __shfl_xor_sync(0xffffffffu, s1, d);
    }
    const float inv0 = 1.f / s0, inv1 = 1.f / s1;

    // ---- O = P V : single-pass fp16 P (packed straight from acc) ------------
    float o[4][4] = {};
    #pragma unroll
    for (int j = 0; j < 4; j++) {
        uint32_t aP[4];
        aP[0] = pack_half2(acc[2*j][0],   acc[2*j][1]);
        aP[1] = pack_half2(acc[2*j][2],   acc[2*j][3]);
        aP[2] = pack_half2(acc[2*j+1][0], acc[2*j+1][1]);
        aP[3] = pack_half2(acc[2*j+1][2], acc[2*j+1][3]);

        uint32_t Bv[4][2];
        #pragma unroll
        for (int a = 0; a < 2; a++) {
            uint32_t row = (uint32_t)(16 * j + lrow + (lblk & 1) * 8);
            uint32_t c16 = (uint32_t)(2 * a + (lblk >> 1));
            uint32_t r[4];
            ldm_x4_trans(r, av + swz(row, c16));
            Bv[2*a][0] = r[0]; Bv[2*a][1] = r[1];
            Bv[2*a+1][0] = r[2]; Bv[2*a+1][1] = r[3];
        }
        #pragma unroll
        for (int nt = 0; nt < 4; nt++) mma16816h(o[nt], aP, Bv[nt]);
    }

    // ---- epilogue: normalize, fp16, stage in smem (reuse sq), store ---------
    __syncthreads();
    {
        int r0 = 16 * wid + (lane >> 2);
        int cb = (lane & 3) * 2;
        #pragma unroll
        for (int nt = 0; nt < 4; nt++) {
            int d = nt * 8 + cb;
            *reinterpret_cast<uint32_t*>(&sq[r0 * 32 + d]) =
                pack_half2(o[nt][0] * inv0, o[nt][1] * inv0);
            *reinterpret_cast<uint32_t*>(&sq[(r0 + 8) * 32 + d]) =
                pack_half2(o[nt][2] * inv1, o[nt][3] * inv1);
        }
    }
    __syncthreads();
    {
        int tok  = tid >> 1;
        int half = tid & 1;
        int wsh = tok >> 3, wsw = tok & 7;
        int pixo = (hh * 8 + wsh) * 64 + ww * 8 + wsw;
        size_t off = ((size_t)b * HW + pixo) * CCH + head * DHEAD + half * 16;
        const uint4* s = reinterpret_cast<const uint4*>(&sq[tok * 32 + half * 16]);
        uint4* d = reinterpret_cast<uint4*>(g_o + off);
        d[0] = s[0];
        d[1] = s[1];
    }
}

// ---------------------------------------------------------------------------
extern "C" void kernel_launch(void* const* d_in, const int* in_sizes, int n_in,
                              void* d_out, int out_size)
{
    const float* x      = (const float*)d_in[0];
    const float* w_qkv  = (const float*)d_in[1];
    const float* b_qkv  = (const float*)d_in[2];
    const float* w_proj = (const float*)d_in[3];
    const float* b_proj = (const float*)d_in[4];
    float* out = (float*)d_out;
    (void)in_sizes; (void)n_in; (void)out_size;

    cudaFuncSetAttribute(gemm_mma_kernel<0>,
                         cudaFuncAttributeMaxDynamicSharedMemorySize, GEMM_SMEM);
    cudaFuncSetAttribute(gemm_mma_kernel<1>,
                         cudaFuncAttributeMaxDynamicSharedMemorySize, GEMM_SMEM);

    // transpose x + (z-slice BATCH) weight fp16 conversion, one launch
    dim3 gT(HW / 32, CCH / 32, BATCH + 1);
    transpose_half_kernel<<<gT, 256>>>(x, w_qkv, w_proj);

    dim3 g1(QKV_C / 128, HW / 128, BATCH);   // n fastest -> A-tile L2 reuse
    gemm_mma_kernel<0><<<g1, 128, GEMM_SMEM>>>(b_qkv, nullptr);

    dim3 gA(64, NHEADS, BATCH);
    attn_mma_kernel<<<gA, 128>>>();

    dim3 g2(CCH / 128, HW / 128, BATCH);
    gemm_mma_kernel<1><<<g2, 128, GEMM_SMEM>>>(b_proj, out);
}

// round 16
// speedup vs baseline: 1.5274x; 1.0053x over previous
#include <cuda_runtime.h>
#include <cuda_fp16.h>
#include <cstdint>

// Problem constants
#define BATCH  16
#define CCH    384
#define HW     4096
#define NHEADS 12
#define DHEAD  32
#define QKV_C  1152

#define BK     64
#define NCHUNK (CCH / BK)   // 6

// ---------------------------------------------------------------------------
// Device-global scratch (no cudaMalloc allowed)
// ---------------------------------------------------------------------------
__device__ __align__(256) __half g_qkv[(size_t)BATCH * HW * QKV_C]; // fp16, q pre-scaled
__device__ __align__(256) __half g_xt[(size_t)BATCH * HW * CCH];    // x^T fp16 [b][pix][c]
__device__ __align__(256) __half g_o [(size_t)BATCH * HW * CCH];    // attn out fp16
__device__ __align__(256) __half g_wq_h[QKV_C * CCH];
__device__ __align__(256) __half g_wp_h[CCH * CCH];

// ---------------------------------------------------------------------------
// Helpers
// ---------------------------------------------------------------------------
__device__ __forceinline__ uint32_t smem_u32(const void* p) {
    uint32_t a;
    asm("{ .reg .u64 t; cvta.to.shared.u64 t, %1; cvt.u32.u64 %0, t; }"
        : "=r"(a) : "l"(p));
    return a;
}

__device__ __forceinline__ uint32_t pack_half2(float a, float b) {
    __half ha = __float2half_rn(a), hb = __float2half_rn(b);
    uint16_t ua = *reinterpret_cast<uint16_t*>(&ha);
    uint16_t ub = *reinterpret_cast<uint16_t*>(&hb);
    return (uint32_t)ua | ((uint32_t)ub << 16);
}

// 32-col tile swizzle (attn): rows of 32 halves (64B), 4x16B chunks
__device__ __forceinline__ uint32_t swz(uint32_t row, uint32_t c16) {
    return row * 64u + ((c16 ^ ((row >> 1) & 3u)) * 16u);
}

// 64-col tile swizzle (gemm): rows of 64 halves (128B), 8x16B chunks
__device__ __forceinline__ uint32_t swz128(uint32_t row, uint32_t c16) {
    return row * 128u + ((c16 ^ (row & 7u)) * 16u);
}

__device__ __forceinline__ void ldm_x4(uint32_t* r, uint32_t addr) {
    asm volatile("ldmatrix.sync.aligned.m8n8.x4.shared.b16 {%0,%1,%2,%3}, [%4];"
                 : "=r"(r[0]), "=r"(r[1]), "=r"(r[2]), "=r"(r[3]) : "r"(addr));
}

__device__ __forceinline__ void ldm_x4_trans(uint32_t* r, uint32_t addr) {
    asm volatile("ldmatrix.sync.aligned.m8n8.x4.trans.shared.b16 {%0,%1,%2,%3}, [%4];"
                 : "=r"(r[0]), "=r"(r[1]), "=r"(r[2]), "=r"(r[3]) : "r"(addr));
}

__device__ __forceinline__ void mma16816h(float* c, const uint32_t* a, const uint32_t* b) {
    asm volatile(
        "mma.sync.aligned.m16n8k16.row.col.f32.f16.f16.f32 "
        "{%0,%1,%2,%3}, {%4,%5,%6,%7}, {%8,%9}, {%0,%1,%2,%3};"
        : "+f"(c[0]), "+f"(c[1]), "+f"(c[2]), "+f"(c[3])
        : "r"(a[0]), "r"(a[1]), "r"(a[2]), "r"(a[3]), "r"(b[0]), "r"(b[1]));
}

#define CP_ASYNC16(dst, src) \
    asm volatile("cp.async.cg.shared.global [%0], [%1], 16;" :: "r"(dst), "l"(src))
#define CP_COMMIT() asm volatile("cp.async.commit_group;")
#define CP_WAIT0()  asm volatile("cp.async.wait_group 0;")
#define CP_WAIT1()  asm volatile("cp.async.wait_group 1;")

// load one ROWSx64 fp16 tile (row stride CCH) into swizzled smem via cp.async
// ROWS*8 chunks of 16B; 128 threads x ROWS/16
template<int ROWS>
__device__ __forceinline__ void load_tileR_async(const __half* __restrict__ src,
                                                 int row0, int k0, uint32_t dst, int tid) {
    #pragma unroll
    for (int j = 0; j < ROWS / 16; j++) {
        int c   = tid + j * 128;
        int row = c >> 3, c16 = c & 7;
        const __half* g = src + (size_t)(row0 + row) * CCH + k0 + c16 * 8;
        CP_ASYNC16(dst + swz128((uint32_t)row, (uint32_t)c16), g);
    }
}

// ---------------------------------------------------------------------------
// Kernel 1: transpose x [b][c][pix] -> fp16 [b][pix][c].
// Extra z-slice (b == BATCH) converts both weight matrices to fp16.
// ---------------------------------------------------------------------------
__global__ __launch_bounds__(256) void transpose_half_kernel(const float* __restrict__ x,
                                                             const float* __restrict__ wq,
                                                             const float* __restrict__ wp)
{
    const int b = blockIdx.z;
    if (b == BATCH) {
        int nblk = gridDim.x * gridDim.y;
        int bid  = blockIdx.y * gridDim.x + blockIdx.x;
        int stride = nblk * 256;
        for (int i = bid * 256 + threadIdx.x; i < QKV_C * CCH; i += stride)
            g_wq_h[i] = __float2half_rn(wq[i]);
        for (int i = bid * 256 + threadIdx.x; i < CCH * CCH; i += stride)
            g_wp_h[i] = __float2half_rn(wp[i]);
        return;
    }

    __shared__ float t[32][33];
    const int p0 = blockIdx.x * 32;
    const int c0 = blockIdx.y * 32;
    const int tx = threadIdx.x & 31;
    const int ty = threadIdx.x >> 5;

    const float* xb = x + (size_t)b * CCH * HW;
    #pragma unroll
    for (int i = 0; i < 4; i++)
        t[ty + i * 8][tx] = xb[(size_t)(c0 + ty + i * 8) * HW + p0 + tx];
    __syncthreads();

    #pragma unroll
    for (int i = 0; i < 4; i++) {
        int p = p0 + ty + i * 8;
        int c = c0 + tx;
        g_xt[((size_t)b * HW + p) * CCH + c] = __float2half_rn(t[tx][ty + i * 8]);
    }
}

// ---------------------------------------------------------------------------
// Tensor-core GEMM (single-pass fp16 mma, fp32 accumulate)
// G==0 (qkv): CTA 128x128, 4 warps (2m x 2n), warp tile 64x64, 2 CTAs/SM.
//             A = g_xt, B = w_qkv -> g_qkv fp16 [b][pix][1152], q pre-scaled.
// G==1 (proj): CTA 64x128, 4 warps (2m x 2n), warp tile 32x64, 3 CTAs/SM
//             (better wave fit: 3072 CTAs). A = g_o, B = w_proj -> fp32 out.
// BK=64, 3-stage cp.async pipeline.
// ---------------------------------------------------------------------------
#define GEMM_SMEM0 98304   // 3 x (16K A + 16K B)
#define GEMM_SMEM1 73728   // 3 x ( 8K A + 16K B)

template<int G>
__global__ __launch_bounds__(128, (G == 0 ? 2 : 3))
void gemm_mma_kernel(const float* __restrict__ bias, float* __restrict__ out_base)
{
    constexpr int MT    = (G == 0 ? 128 : 64);     // m tile
    constexpr int ST    = (G == 0 ? 32768 : 24576); // stage bytes
    constexpr int BOFF  = (G == 0 ? 16384 : 8192);  // B offset within stage
    constexpr int MW    = (G == 0 ? 4 : 2);         // mt fragments per warp

    extern __shared__ __align__(128) char smem[];
    const uint32_t sbase = smem_u32(smem);
    const int tid = threadIdx.x, wid = tid >> 5, lane = tid & 31;
    const int warp_m = wid & 1;        // 2 warps along m
    const int warp_n = wid >> 1;       // 2 warps along n (64 cols each)

    const int b  = blockIdx.z;
    const int n0 = blockIdx.x * 128;   // och tile (x fastest -> A reuse in L2)
    const int m0 = blockIdx.y * MT;    // pixel tile

    const __half* A  = (G == 0 ? g_xt : g_o) + (size_t)b * HW * CCH;
    const __half* Bw = (G == 0 ? g_wq_h : g_wp_h);

    float acc[MW][8][4] = {};

    #pragma unroll
    for (int i = 0; i < 2; i++) {
        const uint32_t sb = sbase + i * ST;
        load_tileR_async<MT>(A,   m0, i * BK, sb + 0,    tid);
        load_tileR_async<128>(Bw, n0, i * BK, sb + BOFF, tid);
        CP_COMMIT();
    }
    CP_WAIT1();
    __syncthreads();

    const int lrow = lane & 7;
    const int lblk = lane >> 3;

    #pragma unroll 1
    for (int i = 0; i < NCHUNK; i++) {
        if (i + 2 < NCHUNK) {
            const uint32_t nb = sbase + ((i + 2) % 3) * ST;
            const int k0 = (i + 2) * BK;
            load_tileR_async<MT>(A,   m0, k0, nb + 0,    tid);
            load_tileR_async<128>(Bw, n0, k0, nb + BOFF, tid);
            CP_COMMIT();
        }

        const uint32_t sA = sbase + (i % 3) * ST;
        const uint32_t sB = sA + BOFF;

        #pragma unroll
        for (int ks = 0; ks < 4; ks++) {
            uint32_t Af[MW][4];
            #pragma unroll
            for (int mt = 0; mt < MW; mt++) {
                uint32_t row = (uint32_t)(warp_m * (MT / 2) + mt * 16 + (lblk & 1) * 8 + lrow);
                uint32_t c16 = (uint32_t)(ks * 2 + (lblk >> 1));
                ldm_x4(Af[mt], sA + swz128(row, c16));
            }
            uint32_t Bf[8][2];
            #pragma unroll
            for (int np = 0; np < 4; np++) {
                uint32_t row = (uint32_t)(warp_n * 64 + np * 16 + (lblk >> 1) * 8 + lrow);
                uint32_t c16 = (uint32_t)(ks * 2 + (lblk & 1));
                uint32_t r[4];
                ldm_x4(r, sB + swz128(row, c16));
                Bf[np*2][0] = r[0]; Bf[np*2][1] = r[1];
                Bf[np*2+1][0] = r[2]; Bf[np*2+1][1] = r[3];
            }
            #pragma unroll
            for (int mt = 0; mt < MW; mt++)
                #pragma unroll
                for (int nt = 0; nt < 8; nt++)
                    mma16816h(acc[mt][nt], Af[mt], Bf[nt]);
        }

        if (i + 2 < NCHUNK)      CP_WAIT1();
        else if (i + 1 < NCHUNK) CP_WAIT0();
        __syncthreads();
    }

    // ------------------- epilogue -------------------
    if (G == 0) {
        constexpr int PADH = 136;   // halves per staged row (272B, 16B-mult)
        const float SCALE = 0.17677669529663687f;
        __half* st = reinterpret_cast<__half*>(smem);   // [128][136]
        {
            #pragma unroll
            for (int mt = 0; mt < MW; mt++)
                #pragma unroll
                for (int nt = 0; nt < 8; nt++) {
                    int ml = warp_m * 64 + mt * 16 + (lane >> 2);
                    int nl = warp_n * 64 + nt * 8 + (lane & 3) * 2;
                    int och = n0 + nl;
                    float s  = (och < CCH) ? SCALE : 1.0f;
                    float b0 = bias[och], b1 = bias[och + 1];
                    *reinterpret_cast<uint32_t*>(&st[ml * PADH + nl]) =
                        pack_half2((acc[mt][nt][0] + b0) * s, (acc[mt][nt][1] + b1) * s);
                    *reinterpret_cast<uint32_t*>(&st[(ml + 8) * PADH + nl]) =
                        pack_half2((acc[mt][nt][2] + b0) * s, (acc[mt][nt][3] + b1) * s);
                }
        }
        __syncthreads();
        __half* outb = g_qkv + (size_t)b * HW * QKV_C;
        #pragma unroll
        for (int j = 0; j < 16; j++) {
            int fi  = tid + j * 128;          // 2048 chunks of 8 halves
            int row = fi >> 4;
            int c16 = fi & 15;
            uint4 v = *reinterpret_cast<uint4*>(&st[row * PADH + c16 * 8]);
            *reinterpret_cast<uint4*>(&outb[(size_t)(m0 + row) * QKV_C + n0 + c16 * 8]) = v;
        }
    } else {
        // stage full 128(och) x 64(pix) fp32 tile, then coalesced store
        constexpr int PAD = 68;   // floats; 68*4 = 272B, 16B mult
        float* st = reinterpret_cast<float*>(smem);     // [128][68] = 34.8KB
        {
            #pragma unroll
            for (int mt = 0; mt < MW; mt++)
                #pragma unroll
                for (int nt = 0; nt < 8; nt++) {
                    int ml = warp_m * 32 + mt * 16 + (lane >> 2);
                    int nl = warp_n * 64 + nt * 8 + (lane & 3) * 2;
                    st[nl * PAD + ml]           = acc[mt][nt][0];
                    st[(nl + 1) * PAD + ml]     = acc[mt][nt][1];
                    st[nl * PAD + ml + 8]       = acc[mt][nt][2];
                    st[(nl + 1) * PAD + ml + 8] = acc[mt][nt][3];
                }
        }
        __syncthreads();
        float* outb = out_base + (size_t)b * CCH * HW;
        #pragma unroll
        for (int j = 0; j < 16; j++) {
            int fi  = tid + j * 128;          // 2048 float4 chunks
            int row = fi >> 4;                // och local 0..127
            int c4  = (fi & 15) * 4;          // pix local
            int och = n0 + row;
            float4 v = *reinterpret_cast<float4*>(&st[row * PAD + c4]);
            float bi = bias[och];
            v.x += bi; v.y += bi; v.z += bi; v.w += bi;
            *reinterpret_cast<float4*>(&outb[(size_t)och * HW + m0 + c4]) = v;
        }
    }
}

// ---------------------------------------------------------------------------
// Attention: 1 block = (b, head, window), 4 warps. All-fp16 operands.
// q pre-scaled by producer. S single-pass; P·V single-pass fp16 (P in [0,1]).
// Strided windows (faithful to reference).
// ---------------------------------------------------------------------------
__global__ __launch_bounds__(128) void attn_mma_kernel()
{
    __shared__ __align__(128) __half sq[64 * 32];
    __shared__ __align__(128) __half sk[64 * 32];
    __shared__ __align__(128) __half sv[64 * 32];

    const int wi   = blockIdx.x;
    const int head = blockIdx.y;
    const int b    = blockIdx.z;
    const int hh   = wi >> 3;
    const int ww   = wi & 7;
    const int tid  = threadIdx.x;
    const int wid  = tid >> 5;
    const int lane = tid & 31;

    const uint32_t aq = smem_u32(sq), ak = smem_u32(sk), av = smem_u32(sv);

    const __half* base = g_qkv + (size_t)b * HW * QKV_C + (size_t)head * DHEAD;

    #pragma unroll
    for (int it = 0; it < 6; it++) {
        int e   = tid + it * 128;
        int ten = e >> 8;              // 0=q 1=k 2=v
        int rem = e & 255;
        int tok = rem >> 2;
        int c16 = rem & 3;
        int wsh = tok >> 3, wsw = tok & 7;
        int pix = (wsh * 8 + hh) * 64 + wsw * 8 + ww;
        const __half* g = base + (size_t)pix * QKV_C + ten * CCH + c16 * 8;
        uint32_t dst = (ten == 0 ? aq : ten == 1 ? ak : av) + swz((uint32_t)tok, (uint32_t)c16);
        CP_ASYNC16(dst, g);
    }
    CP_COMMIT();
    CP_WAIT0();
    __syncthreads();

    const int lrow = lane & 7;
    const int lblk = lane >> 3;

    // ---- S = Q K^T (q pre-scaled), single-pass fp16 -------------------------
    float acc[8][4] = {};
    #pragma unroll
    for (int ks = 0; ks < 2; ks++) {
        uint32_t Af[4];
        {
            uint32_t row = (uint32_t)(wid * 16 + (lblk & 1) * 8 + lrow);
            uint32_t c16 = (uint32_t)(ks * 2 + (lblk >> 1));
            ldm_x4(Af, aq + swz(row, c16));
        }
        uint32_t Bf[8][2];
        #pragma unroll
        for (int np = 0; np < 4; np++) {
            uint32_t row = (uint32_t)(np * 16 + (lblk >> 1) * 8 + lrow);
            uint32_t c16 = (uint32_t)(ks * 2 + (lblk & 1));
            uint32_t r[4];
            ldm_x4(r, ak + swz(row, c16));
            Bf[np*2][0] = r[0]; Bf[np*2][1] = r[1];
            Bf[np*2+1][0] = r[2]; Bf[np*2+1][1] = r[3];
        }
        #pragma unroll
        for (int nt = 0; nt < 8; nt++) mma16816h(acc[nt], Af, Bf[nt]);
    }

    // ---- softmax in registers ----------------------------------------------
    float mx0 = -1e30f, mx1 = -1e30f;
    #pragma unroll
    for (int nt = 0; nt < 8; nt++) {
        mx0 = fmaxf(mx0, fmaxf(acc[nt][0], acc[nt][1]));
        mx1 = fmaxf(mx1, fmaxf(acc[nt][2], acc[nt][3]));
    }
    #pragma unroll
    for (int d = 1; d <= 2; d <<= 1) {
        mx0 = fmaxf(mx0, __shfl_xor_sync(0xffffffffu, mx0, d));
        mx1 = fmaxf(mx1, __shfl_xor_sync(0xffffffffu, mx1, d));
    }
    float s0 = 0.f, s1 = 0.f;
    #pragma unroll
    for (int nt = 0; nt < 8; nt++) {
        acc[nt][0] = __expf(acc[nt][0] - mx0);
        acc[nt][1] = __expf(acc[nt][1] - mx0);
        acc[nt][2] = __expf(acc[nt][2] - mx1);
        acc[nt][3] = __expf(acc[nt][3] - mx1);
        s0 += acc[nt][0] + acc[nt][1];
        s1 += acc[nt][2] + acc[nt][3];
    }
    #pragma unroll
    for (int d = 1; d <= 2; d <<= 1) {
        s0 += __shfl_xor_sync(0xffffffffu, s0, d);
        s1 += __shfl_xor_sync(0xffffffffu, s1, d);
    }
    const float inv0 = 1.f / s0, inv1 = 1.f / s1;

    // ---- O = P V : single-pass fp16 P (packed straight from acc) ------------
    float o[4][4] = {};
    #pragma unroll
    for (int j = 0; j < 4; j++) {
        uint32_t aP[4];
        aP[0] = pack_half2(acc[2*j][0],   acc[2*j][1]);
        aP[1] = pack_half2(acc[2*j][2],   acc[2*j][3]);
        aP[2] = pack_half2(acc[2*j+1][0], acc[2*j+1][1]);
        aP[3] = pack_half2(acc[2*j+1][2], acc[2*j+1][3]);

        uint32_t Bv[4][2];
        #pragma unroll
        for (int a = 0; a < 2; a++) {
            uint32_t row = (uint32_t)(16 * j + lrow + (lblk & 1) * 8);
            uint32_t c16 = (uint32_t)(2 * a + (lblk >> 1));
            uint32_t r[4];
            ldm_x4_trans(r, av + swz(row, c16));
            Bv[2*a][0] = r[0]; Bv[2*a][1] = r[1];
            Bv[2*a+1][0] = r[2]; Bv[2*a+1][1] = r[3];
        }
        #pragma unroll
        for (int nt = 0; nt < 4; nt++) mma16816h(o[nt], aP, Bv[nt]);
    }

    // ---- epilogue: normalize, fp16, stage in smem (reuse sq), store ---------
    __syncthreads();
    {
        int r0 = 16 * wid + (lane >> 2);
        int cb = (lane & 3) * 2;
        #pragma unroll
        for (int nt = 0; nt < 4; nt++) {
            int d = nt * 8 + cb;
            *reinterpret_cast<uint32_t*>(&sq[r0 * 32 + d]) =
                pack_half2(o[nt][0] * inv0, o[nt][1] * inv0);
            *reinterpret_cast<uint32_t*>(&sq[(r0 + 8) * 32 + d]) =
                pack_half2(o[nt][2] * inv1, o[nt][3] * inv1);
        }
    }
    __syncthreads();
    {
        int tok  = tid >> 1;
        int half = tid & 1;
        int wsh = tok >> 3, wsw = tok & 7;
        int pixo = (hh * 8 + wsh) * 64 + ww * 8 + wsw;
        size_t off = ((size_t)b * HW + pixo) * CCH + head * DHEAD + half * 16;
        const uint4* s = reinterpret_cast<const uint4*>(&sq[tok * 32 + half * 16]);
        uint4* d = reinterpret_cast<uint4*>(g_o + off);
        d[0] = s[0];
        d[1] = s[1];
    }
}

// ---------------------------------------------------------------------------
extern "C" void kernel_launch(void* const* d_in, const int* in_sizes, int n_in,
                              void* d_out, int out_size)
{
    const float* x      = (const float*)d_in[0];
    const float* w_qkv  = (const float*)d_in[1];
    const float* b_qkv  = (const float*)d_in[2];
    const float* w_proj = (const float*)d_in[3];
    const float* b_proj = (const float*)d_in[4];
    float* out = (float*)d_out;
    (void)in_sizes; (void)n_in; (void)out_size;

    cudaFuncSetAttribute(gemm_mma_kernel<0>,
                         cudaFuncAttributeMaxDynamicSharedMemorySize, GEMM_SMEM0);
    cudaFuncSetAttribute(gemm_mma_kernel<1>,
                         cudaFuncAttributeMaxDynamicSharedMemorySize, GEMM_SMEM1);

    // transpose x + (z-slice BATCH) weight fp16 conversion, one launch
    dim3 gT(HW / 32, CCH / 32, BATCH + 1);
    transpose_half_kernel<<<gT, 256>>>(x, w_qkv, w_proj);

    dim3 g1(QKV_C / 128, HW / 128, BATCH);   // n fastest -> A-tile L2 reuse
    gemm_mma_kernel<0><<<g1, 128, GEMM_SMEM0>>>(b_qkv, nullptr);

    dim3 gA(64, NHEADS, BATCH);
    attn_mma_kernel<<<gA, 128>>>();

    dim3 g2(CCH / 128, HW / 64, BATCH);      // 3 x 64 x 16 = 3072 CTAs
    gemm_mma_kernel<1><<<g2, 128, GEMM_SMEM1>>>(b_proj, out);
}